// round 17
// baseline (speedup 1.0000x reference)
#include <cuda_runtime.h>
#include <cuda_fp16.h>
#include <cstdint>
#include <cmath>

// ============================================================================
// B=4096 features [B,256], K=8192 centroids [K,256], weight [B]
//   c = normalize(centroids, dim=1)
//   prod = features @ c.T / 0.07   -> per-row max m[b], argmax pos[b]
//   S[k] = sum_j exp((c @ c.T / 0.07)[j,k])
//   pep = exp(m)*w ; J = logf(pep) - logf(pep + S[pos]) ; out = -mean(J)
//
// R16 -> R17: (1) liveness-checked ldsm/MMA interleave in the 256x128 gemm
// (peak ~122 regs, fits occ-2 128-reg cap); (2) prep with MLP=4 feature
// loads; (3) final reduction fused into k_gemm's last CTA (threadfence +
// counter). 2 launches total.
// ============================================================================

#define B_ROWS 4096
#define K_ROWS 8192
#define D_DIM  256
#define X_ROWS (B_ROWS + K_ROWS)
#define MT     256
#define NT     128
#define F_MT   (B_ROWS / MT)                     // 16
#define NTILES (K_ROWS / NT)                     // 64
#define FEAT_CTAS (F_MT * NTILES)                // 1024
#define CENT_CTAS 1056                           // sum_i (64 - 2i), i<32
#define TOTAL_CTAS (FEAT_CTAS + CENT_CTAS)       // 2080
#define INV_T  14.285714285714285714f            // 1/0.07

#define ROW_BYTES  80
#define A_CHUNK (MT * ROW_BYTES)                 // 20480
#define B_CHUNK (NT * ROW_BYTES)                 // 10240
#define STAGE_BYTES (A_CHUNK + B_CHUNK)          // 30720
#define SMEM_BYTES  (2 * STAGE_BYTES)            // 61440 (needs attribute)
#define NCHUNK 8

__device__ __half g_X[(size_t)X_ROWS * D_DIM];
__device__ float g_S[K_ROWS];
__device__ unsigned long long g_max[B_ROWS];
__device__ float g_sum;
__device__ unsigned g_done;

// ---------------- helpers ----------------------------------------------------

static __device__ __forceinline__ uint32_t smem_u32(const void* p) {
    uint32_t a;
    asm("{ .reg .u64 t; cvta.to.shared.u64 t, %1; cvt.u32.u64 %0, t; }"
        : "=r"(a) : "l"(p));
    return a;
}

static __device__ __forceinline__ void cp16(uint32_t dst, const void* src) {
    asm volatile("cp.async.cg.shared.global [%0], [%1], 16;"
                 :: "r"(dst), "l"(src));
}

static __device__ __forceinline__ void ldsm4(uint32_t& r0, uint32_t& r1,
                                             uint32_t& r2, uint32_t& r3,
                                             uint32_t addr) {
    asm volatile("ldmatrix.sync.aligned.m8n8.x4.shared.b16 {%0,%1,%2,%3}, [%4];"
                 : "=r"(r0), "=r"(r1), "=r"(r2), "=r"(r3) : "r"(addr));
}

// fp16 in, fp16 acc. reg h, half j <-> row (g + 8h), col (quad*2 + j)
static __device__ __forceinline__ void mma16816h(uint32_t* c, const uint32_t* a,
                                                 const uint32_t* b) {
    asm("mma.sync.aligned.m16n8k16.row.col.f16.f16.f16.f16 "
        "{%0,%1}, {%2,%3,%4,%5}, {%6,%7}, {%0,%1};"
        : "+r"(c[0]), "+r"(c[1])
        : "r"(a[0]), "r"(a[1]), "r"(a[2]), "r"(a[3]), "r"(b[0]), "r"(b[1]));
}

// ---------------- merged prep -------------------------------------------------
// blocks [0,256): feature fp16 convert, 4 float4/thread (MLP=4) + state zero.
// blocks [256,1280): centroid normalize (8 rows/block, one warp per row).

__global__ void k_prep(const float4* __restrict__ f4,
                       const float* __restrict__ cent) {
    const int bid = blockIdx.x;
    if (bid < 256) {
        int base = bid * 1024 + threadIdx.x;
        float4 v0 = f4[base];
        float4 v1 = f4[base + 256];
        float4 v2 = f4[base + 512];
        float4 v3 = f4[base + 768];
        __half2* dst = reinterpret_cast<__half2*>(g_X);
        dst[(base)       * 2]     = __floats2half2_rn(v0.x, v0.y);
        dst[(base)       * 2 + 1] = __floats2half2_rn(v0.z, v0.w);
        dst[(base + 256) * 2]     = __floats2half2_rn(v1.x, v1.y);
        dst[(base + 256) * 2 + 1] = __floats2half2_rn(v1.z, v1.w);
        dst[(base + 512) * 2]     = __floats2half2_rn(v2.x, v2.y);
        dst[(base + 512) * 2 + 1] = __floats2half2_rn(v2.z, v2.w);
        dst[(base + 768) * 2]     = __floats2half2_rn(v3.x, v3.y);
        dst[(base + 768) * 2 + 1] = __floats2half2_rn(v3.z, v3.w);
        int gid = bid * 256 + threadIdx.x;            // 65536 threads
        if (gid < K_ROWS) g_S[gid] = 0.0f;
        if (gid < B_ROWS) g_max[gid] = 0ull;
        if (gid == 0) { g_sum = 0.0f; g_done = 0u; }
    } else {
        int wid = threadIdx.x >> 5, lid = threadIdx.x & 31;
        int k = (bid - 256) * 8 + wid;                // 8192 rows
        const float4* row = reinterpret_cast<const float4*>(cent + (size_t)k * D_DIM);
        float4 v0 = row[lid], v1 = row[lid + 32];
        float s = v0.x * v0.x + v0.y * v0.y + v0.z * v0.z + v0.w * v0.w
                + v1.x * v1.x + v1.y * v1.y + v1.z * v1.z + v1.w * v1.w;
        #pragma unroll
        for (int o = 16; o; o >>= 1) s += __shfl_xor_sync(~0u, s, o);
        float sc = 1.0f / fmaxf(sqrtf(s), 1e-12f);
        __half2* dst = reinterpret_cast<__half2*>(g_X + (size_t)(B_ROWS + k) * D_DIM);
        dst[lid * 2 + 0]  = __floats2half2_rn(v0.x * sc, v0.y * sc);
        dst[lid * 2 + 1]  = __floats2half2_rn(v0.z * sc, v0.w * sc);
        dst[lid * 2 + 64] = __floats2half2_rn(v1.x * sc, v1.y * sc);
        dst[lid * 2 + 65] = __floats2half2_rn(v1.z * sc, v1.w * sc);
    }
}

// ---------------- fused GEMM + epilogue + last-CTA final ----------------------
// grid = 2080 CTAs. 8 warps: wm = wid>>1 (0..3), wn = wid&1. Warp tile 64x64.

__global__ void __launch_bounds__(256, 2) k_gemm(const float* __restrict__ w,
                                                 float* __restrict__ out,
                                                 int out_size) {
    const int bid = blockIdx.x;
    const bool is_feat = (bid < FEAT_CTAS);
    int arow_base, ntile, ci = 0;
    bool row_sums = false;
    if (is_feat) {
        arow_base = (bid >> 6) * MT;
        ntile = bid & 63;
    } else {
        int t = bid - FEAT_CTAS;                      // 0..1055
        int i = (int)((65.0f - sqrtf(65.0f * 65.0f - 4.0f * (float)t)) * 0.5f);
        if (i < 0) i = 0;
        while (65 * (i + 1) - (i + 1) * (i + 1) <= t) i++;
        while (65 * i - i * i > t) i--;
        int off = t - (65 * i - i * i);
        ci = i;
        ntile = 2 * i + off;
        arow_base = B_ROWS + ci * MT;
        row_sums = (off >= 2);
    }

    extern __shared__ char smem[];
    const uint32_t sb = smem_u32(smem);
    const int tid = threadIdx.x;
    const int wid = tid >> 5, lid = tid & 31;
    const int wm = wid >> 1, wn = wid & 1;

    const __half* gA = g_X + (size_t)arow_base * D_DIM;
    const __half* gB = g_X + (size_t)(B_ROWS + ntile * NT) * D_DIM;

    uint32_t acc[4][8][2];                            // 64 regs (f16x2)
    #pragma unroll
    for (int a = 0; a < 4; a++)
        #pragma unroll
        for (int b = 0; b < 8; b++) { acc[a][b][0] = 0u; acc[a][b][1] = 0u; }

    const int rA = tid >> 2, cA = tid & 3;

    // ---- prefetch chunk 0 ----
    {
        #pragma unroll
        for (int i = 0; i < 4; i++) {
            int row = rA + i * 64;
            cp16(sb + (uint32_t)(row * ROW_BYTES + cA * 16),
                 gA + (size_t)row * D_DIM + cA * 8);
        }
        #pragma unroll
        for (int i = 0; i < 2; i++) {
            int row = rA + i * 64;
            cp16(sb + A_CHUNK + (uint32_t)(row * ROW_BYTES + cA * 16),
                 gB + (size_t)row * D_DIM + cA * 8);
        }
    }
    asm volatile("cp.async.commit_group;" ::: "memory");

    const int arow = lid & 15, asel = lid >> 4;
    const int brow = lid & 7;
    const int bsel = lid >> 3;
    const int bn_off = 8 * (bsel >> 1), bk_off = 8 * (bsel & 1);

    #pragma unroll
    for (int kc = 0; kc < NCHUNK; kc++) {
        __syncthreads();   // retire reads of the stage about to be overwritten

        if (kc < NCHUNK - 1) {
            const int nk = kc + 1;
            const uint32_t stage = (uint32_t)(nk & 1) * STAGE_BYTES;
            #pragma unroll
            for (int i = 0; i < 4; i++) {
                int row = rA + i * 64;
                cp16(sb + stage + (uint32_t)(row * ROW_BYTES + cA * 16),
                     gA + (size_t)row * D_DIM + nk * 32 + cA * 8);
            }
            #pragma unroll
            for (int i = 0; i < 2; i++) {
                int row = rA + i * 64;
                cp16(sb + stage + A_CHUNK + (uint32_t)(row * ROW_BYTES + cA * 16),
                     gB + (size_t)row * D_DIM + nk * 32 + cA * 8);
            }
            asm volatile("cp.async.commit_group;" ::: "memory");
            asm volatile("cp.async.wait_group 1;" ::: "memory");
        } else {
            asm volatile("cp.async.wait_group 0;" ::: "memory");
        }
        __syncthreads();   // publish chunk kc

        const uint32_t sA = sb + (uint32_t)(kc & 1) * STAGE_BYTES;
        const uint32_t sB = sA + A_CHUNK;

        // ---- interleaved chunk body (peak live ~122 regs) ----
        uint32_t a0[4][4], b0[8][2], b1[8][2];

        // ldsm A0, B0 (ks0)
        #pragma unroll
        for (int mf = 0; mf < 4; mf++) {
            uint32_t ad = sA + (uint32_t)((wm * 64 + mf * 16 + arow) * ROW_BYTES
                                          + (8 * asel) * 2);
            ldsm4(a0[mf][0], a0[mf][1], a0[mf][2], a0[mf][3], ad);
        }
        #pragma unroll
        for (int half = 0; half < 4; half++) {
            uint32_t bd = sB + (uint32_t)((wn * 64 + half * 16 + bn_off + brow) * ROW_BYTES
                                          + bk_off * 2);
            ldsm4(b0[half * 2][0], b0[half * 2][1],
                  b0[half * 2 + 1][0], b0[half * 2 + 1][1], bd);
        }

        // MMA ks0 mf0,mf1
        #pragma unroll
        for (int mf = 0; mf < 2; mf++)
            #pragma unroll
            for (int nf = 0; nf < 8; nf++)
                mma16816h(acc[mf][nf], a0[mf], b0[nf]);

        // ldsm B1 (ks1) under mf2,mf3 MMAs
        #pragma unroll
        for (int half = 0; half < 4; half++) {
            uint32_t bd = sB + (uint32_t)((wn * 64 + half * 16 + bn_off + brow) * ROW_BYTES
                                          + (16 + bk_off) * 2);
            ldsm4(b1[half * 2][0], b1[half * 2][1],
                  b1[half * 2 + 1][0], b1[half * 2 + 1][1], bd);
        }
        #pragma unroll
        for (int mf = 2; mf < 4; mf++)
            #pragma unroll
            for (int nf = 0; nf < 8; nf++)
                mma16816h(acc[mf][nf], a0[mf], b0[nf]);

        // ldsm A1 (reuses A0's registers), then MMA ks1
        #pragma unroll
        for (int mf = 0; mf < 4; mf++) {
            uint32_t ad = sA + (uint32_t)((wm * 64 + mf * 16 + arow) * ROW_BYTES
                                          + (16 + 8 * asel) * 2);
            ldsm4(a0[mf][0], a0[mf][1], a0[mf][2], a0[mf][3], ad);
        }
        #pragma unroll
        for (int mf = 0; mf < 4; mf++)
            #pragma unroll
            for (int nf = 0; nf < 8; nf++)
                mma16816h(acc[mf][nf], a0[mf], b1[nf]);
    }

    // ---- epilogue (acc reg h holds cols {quad*2, quad*2+1} of row g+8h) ----
    const int quad = lid & 3, g = lid >> 2;
    if (is_feat) {
        #pragma unroll
        for (int mf = 0; mf < 4; mf++) {
            #pragma unroll
            for (int h = 0; h < 2; h++) {
                float best = -3.4e38f;
                int bc = 0;
                #pragma unroll
                for (int nf = 0; nf < 8; nf++) {
                    __half2 hv = *reinterpret_cast<__half2*>(&acc[mf][nf][h]);
                    float v0 = __low2float(hv) * INV_T;
                    float v1 = __high2float(hv) * INV_T;
                    int col0 = ntile * NT + wn * 64 + nf * 8 + quad * 2;
                    if (v0 > best || (v0 == best && col0 < bc)) { best = v0; bc = col0; }
                    if (v1 > best || (v1 == best && col0 + 1 < bc)) { best = v1; bc = col0 + 1; }
                }
                #pragma unroll
                for (int m = 1; m <= 2; m <<= 1) {
                    float ov = __shfl_xor_sync(~0u, best, m);
                    int oc = __shfl_xor_sync(~0u, bc, m);
                    if (ov > best || (ov == best && oc < bc)) { best = ov; bc = oc; }
                }
                if (quad == 0) {
                    int row = arow_base + wm * 64 + mf * 16 + g + 8 * h;
                    unsigned bits = __float_as_uint(best);
                    unsigned u = (bits & 0x80000000u) ? ~bits : (bits | 0x80000000u);
                    unsigned long long packed =
                        ((unsigned long long)u << 32) |
                        (unsigned long long)(0xFFFFFFFFu - (unsigned)bc);
                    atomicMax(&g_max[row], packed);
                }
            }
        }
    } else {
        #pragma unroll
        for (int nf = 0; nf < 8; nf++) {
            #pragma unroll
            for (int j = 0; j < 2; j++) {
                float s = 0.0f;
                #pragma unroll
                for (int mf = 0; mf < 4; mf++) {
                    __half2 h0 = *reinterpret_cast<__half2*>(&acc[mf][nf][0]);
                    __half2 h1 = *reinterpret_cast<__half2*>(&acc[mf][nf][1]);
                    float lo = j ? __high2float(h0) : __low2float(h0);
                    float hi = j ? __high2float(h1) : __low2float(h1);
                    s += __expf(lo * INV_T);
                    s += __expf(hi * INV_T);
                }
                #pragma unroll
                for (int m = 4; m <= 16; m <<= 1)
                    s += __shfl_xor_sync(~0u, s, m);
                if (g == 0)
                    atomicAdd(&g_S[ntile * NT + wn * 64 + nf * 8 + quad * 2 + j], s);
            }
        }
        if (row_sums) {
            #pragma unroll
            for (int mf = 0; mf < 4; mf++) {
                #pragma unroll
                for (int h = 0; h < 2; h++) {
                    float s = 0.0f;
                    #pragma unroll
                    for (int nf = 0; nf < 8; nf++) {
                        __half2 hv = *reinterpret_cast<__half2*>(&acc[mf][nf][h]);
                        s += __expf(__low2float(hv) * INV_T);
                        s += __expf(__high2float(hv) * INV_T);
                    }
                    #pragma unroll
                    for (int m = 1; m <= 2; m <<= 1)
                        s += __shfl_xor_sync(~0u, s, m);
                    if (quad == 0)
                        atomicAdd(&g_S[ci * MT + wm * 64 + mf * 16 + g + 8 * h], s);
                }
            }
        }
    }

    // ---- last-CTA final reduction ----
    __shared__ unsigned s_last;
    __shared__ float ws[8];
    __threadfence();                 // make this CTA's atomics globally visible
    __syncthreads();
    if (tid == 0) s_last = atomicAdd(&g_done, 1u);
    __syncthreads();
    if (s_last == TOTAL_CTAS - 1) {
        float acc_j = 0.0f;
        for (int b = tid; b < B_ROWS; b += 256) {
            unsigned long long p = g_max[b];
            float J = 0.0f;
            if (p != 0ull) {
                unsigned u = (unsigned)(p >> 32);
                int col = (int)(0xFFFFFFFFu - (unsigned)(p & 0xFFFFFFFFull));
                float m = (u & 0x80000000u) ? __uint_as_float(u & 0x7FFFFFFFu)
                                            : __uint_as_float(~u);
                float pep = expf(m) * w[b];
                float Sv  = (col >= 0 && col < K_ROWS) ? g_S[col] : 0.0f;
                J = logf(pep) - logf(pep + Sv);
                if (isnan(J)) J = 0.0f;
            }
            acc_j += J;
        }
        #pragma unroll
        for (int o = 16; o; o >>= 1) acc_j += __shfl_xor_sync(~0u, acc_j, o);
        if (lid == 0) ws[wid] = acc_j;
        __syncthreads();
        if (tid == 0) {
            float s = 0.0f;
            #pragma unroll
            for (int i = 0; i < 8; i++) s += ws[i];
            out[0] = -(s / (float)B_ROWS);
        }
        for (int i = 1 + tid; i < out_size; i += 256) out[i] = 0.0f;
    }
}

// ---------------- launch ------------------------------------------------------

extern "C" void kernel_launch(void* const* d_in, const int* in_sizes, int n_in,
                              void* d_out, int out_size) {
    const float* features  = nullptr;
    const float* centroids = nullptr;
    const float* weight    = nullptr;
    for (int i = 0; i < n_in; i++) {
        if (in_sizes[i] == B_ROWS * D_DIM)      features  = (const float*)d_in[i];
        else if (in_sizes[i] == K_ROWS * D_DIM) centroids = (const float*)d_in[i];
        else if (in_sizes[i] == B_ROWS)         weight    = (const float*)d_in[i];
    }
    float* out = (float*)d_out;

    cudaFuncSetAttribute(k_gemm, cudaFuncAttributeMaxDynamicSharedMemorySize,
                         SMEM_BYTES);

    k_prep<<<1280, 256>>>((const float4*)features, centroids);
    k_gemm<<<TOTAL_CTAS, 256, SMEM_BYTES>>>(weight, out, out_size);
}